// round 4
// baseline (speedup 1.0000x reference)
#include <cuda_runtime.h>
#include <cuda_bf16.h>
#include <cstdint>

// Shapes
#define BB 4
#define NN 4096          // H*W
#define CC 256
#define CK 32

// Scratch (device globals are the allowed scratch mechanism)
__device__ float d_F[BB * NN * CK];         // 2 MB
__device__ float d_G[BB * NN * CK];         // 2 MB
__device__ float d_H[(size_t)BB * NN * CC]; // 16 MB

// ---------------- packed f32x2 helpers ----------------
__device__ __forceinline__ unsigned long long pack2(float lo, float hi) {
    unsigned long long r;
    asm("mov.b64 %0, {%1, %2};" : "=l"(r) : "f"(lo), "f"(hi));
    return r;
}
__device__ __forceinline__ void unpack2(unsigned long long v, float& lo, float& hi) {
    asm("mov.b64 {%0, %1}, %2;" : "=f"(lo), "=f"(hi) : "l"(v));
}
__device__ __forceinline__ void fma2(unsigned long long& d, unsigned long long a,
                                     unsigned long long b) {
    asm("fma.rn.f32x2 %0, %1, %2, %3;" : "=l"(d) : "l"(a), "l"(b), "l"(d));
}
__device__ __forceinline__ void mul2(unsigned long long& d, unsigned long long a,
                                     unsigned long long b) {
    asm("mul.rn.f32x2 %0, %1, %2;" : "=l"(d) : "l"(a), "l"(b));
}

// =====================================================================
// Kernel 1: projections.  Per block: 64 pixels.  5 output chunks of 64
// (chunk 0 = f|g concatenated, chunks 1..4 = hh cols), K in 4 chunks of 64.
// =====================================================================
__global__ __launch_bounds__(256) void proj_kernel(
    const float* __restrict__ x,
    const float* __restrict__ Wf, const float* __restrict__ bfv,
    const float* __restrict__ Wg, const float* __restrict__ bgv,
    const float* __restrict__ Wh, const float* __restrict__ bhv)
{
    __shared__ float xs[64][64];   // 16 KB: [pixel][k]
    __shared__ float ws[64][64];   // 16 KB: [k][out]

    const int t = threadIdx.x;
    const int pix0 = blockIdx.x * 64;
    const int pg = t >> 4;   // pixel group (4 pixels)
    const int og = t & 15;   // out group (4 outputs)

    for (int oc = 0; oc < 5; oc++) {
        float acc[4][4];
#pragma unroll
        for (int i = 0; i < 4; i++)
#pragma unroll
            for (int j = 0; j < 4; j++) acc[i][j] = 0.f;

        for (int kc = 0; kc < 4; kc++) {
            __syncthreads();
            // load x tile [64 px][64 k]
            for (int i = t; i < 1024; i += 256) {
                int px = i >> 4;
                int kq = i & 15;
                *(float4*)&xs[px][kq * 4] =
                    *(const float4*)&x[(size_t)(pix0 + px) * CC + kc * 64 + kq * 4];
            }
            // load weight tile [64 k][64 out]
            for (int i = t; i < 4096; i += 256) {
                int k = i >> 6;
                int o = i & 63;
                int kg = kc * 64 + k;
                float v;
                if (oc == 0)
                    v = (o < 32) ? Wf[kg * CK + o] : Wg[kg * CK + (o - 32)];
                else
                    v = Wh[kg * CC + (oc - 1) * 64 + o];
                ws[k][o] = v;
            }
            __syncthreads();

#pragma unroll 8
            for (int k = 0; k < 64; k++) {
                float4 wv = *(const float4*)&ws[k][og * 4];
                float xv0 = xs[pg * 4 + 0][k];
                float xv1 = xs[pg * 4 + 1][k];
                float xv2 = xs[pg * 4 + 2][k];
                float xv3 = xs[pg * 4 + 3][k];
                acc[0][0] += xv0 * wv.x; acc[0][1] += xv0 * wv.y;
                acc[0][2] += xv0 * wv.z; acc[0][3] += xv0 * wv.w;
                acc[1][0] += xv1 * wv.x; acc[1][1] += xv1 * wv.y;
                acc[1][2] += xv1 * wv.z; acc[1][3] += xv1 * wv.w;
                acc[2][0] += xv2 * wv.x; acc[2][1] += xv2 * wv.y;
                acc[2][2] += xv2 * wv.z; acc[2][3] += xv2 * wv.w;
                acc[3][0] += xv3 * wv.x; acc[3][1] += xv3 * wv.y;
                acc[3][2] += xv3 * wv.z; acc[3][3] += xv3 * wv.w;
            }
        }

        // write back with bias
#pragma unroll
        for (int i = 0; i < 4; i++) {
            int px = pix0 + pg * 4 + i;
#pragma unroll
            for (int j = 0; j < 4; j++) {
                int o = og * 4 + j;
                float v = acc[i][j];
                if (oc == 0) {
                    if (o < 32) d_F[px * CK + o] = v + bfv[o];
                    else        d_G[px * CK + (o - 32)] = v + bgv[o - 32];
                } else {
                    int oo = (oc - 1) * 64 + o;
                    d_H[(size_t)px * CC + oo] = v + bhv[oo];
                }
            }
        }
    }
}

// =====================================================================
// Kernel 2: flash attention + residual.  STATIC smem < 48 KB (no attr).
// Block: 64 queries of one batch, 256 threads.
// Thread: 4 queries (qg = t>>4) x 16 channels (cg = t&15).
// Key tiles of 16 staged in smem; online softmax; packed f32x2 PV.
// =====================================================================
#define JT 16

__global__ __launch_bounds__(256, 2) void flash_kernel(
    const float* __restrict__ x, float* __restrict__ out)
{
    __shared__ float hs[JT * CC];     // 16 KB  hh tile [16][256]
    __shared__ float fs[JT * 36];     // 2.25KB f tile padded [16][36]
    __shared__ float gs[64 * CK];     // 8 KB   g tile [64][32]
    __shared__ float ss[64 * 17];     // 4.25KB p tile padded [64][17]

    const int t = threadIdx.x;
    const int b = blockIdx.x >> 6;
    const int qt = blockIdx.x & 63;
    const int qg = t >> 4;      // 0..15
    const int cg = t & 15;      // 0..15
    const int qbase = qg * 4;

    const float* Fb = d_F + (size_t)b * NN * CK;
    const float* Hb = d_H + (size_t)b * NN * CC;
    const float* Gb = d_G + ((size_t)b * NN + qt * 64) * CK;

    // load g tile (64 x 32) into smem
    for (int i = t; i < 64 * CK / 4; i += 256)
        ((float4*)gs)[i] = ((const float4*)Gb)[i];

    unsigned long long acc[4][8];
#pragma unroll
    for (int qi = 0; qi < 4; qi++)
#pragma unroll
        for (int u = 0; u < 8; u++) acc[qi][u] = 0ull;

    float m[4], l[4];
#pragma unroll
    for (int qi = 0; qi < 4; qi++) { m[qi] = -1e30f; l[qi] = 0.f; }

    for (int j0 = 0; j0 < NN; j0 += JT) {
        __syncthreads();
        // f tile [16][32] -> fs padded [16][36]
        if (t < 128) {
            int r = t >> 3;          // 0..15
            int c4 = t & 7;          // 0..7
            float4 v = *(const float4*)&Fb[(size_t)(j0 + r) * CK + c4 * 4];
            *(float4*)&fs[r * 36 + c4 * 4] = v;
        }
        // hh tile [16][256] = 1024 float4
        {
            const float4* src = (const float4*)&Hb[(size_t)j0 * CC];
            float4* dst = (float4*)hs;
#pragma unroll
            for (int i = 0; i < 4; i++) dst[t + 256 * i] = src[t + 256 * i];
        }
        __syncthreads();

        // ---- scores: thread computes s[q][cg] for its 4 q ----
        float sv[4];
#pragma unroll
        for (int qi = 0; qi < 4; qi++) sv[qi] = 0.f;
#pragma unroll
        for (int k = 0; k < CK; k += 4) {
            float4 f0 = *(const float4*)&fs[cg * 36 + k];
#pragma unroll
            for (int qi = 0; qi < 4; qi++) {
                float4 gq = *(const float4*)&gs[(qbase + qi) * CK + k];
                sv[qi] += gq.x * f0.x + gq.y * f0.y + gq.z * f0.z + gq.w * f0.w;
            }
        }

        // ---- online softmax update (reductions over 16-lane qg group) ----
#pragma unroll
        for (int qi = 0; qi < 4; qi++) {
            float v = sv[qi];
#pragma unroll
            for (int o = 1; o < 16; o <<= 1)
                v = fmaxf(v, __shfl_xor_sync(0xffffffffu, v, o));
            float mnew = fmaxf(m[qi], v);
            float scale = __expf(m[qi] - mnew);
            float p0 = __expf(sv[qi] - mnew);
            float lsum = p0;
#pragma unroll
            for (int o = 1; o < 16; o <<= 1)
                lsum += __shfl_xor_sync(0xffffffffu, lsum, o);
            l[qi] = l[qi] * scale + lsum;
            m[qi] = mnew;
            ss[(qbase + qi) * 17 + cg] = p0;
            unsigned long long s2 = pack2(scale, scale);
#pragma unroll
            for (int u = 0; u < 8; u++) mul2(acc[qi][u], acc[qi][u], s2);
        }
        __syncwarp();

        // ---- PV: o += p * hh, packed f32x2 ----
#pragma unroll 2
        for (int j = 0; j < JT; j++) {
            unsigned long long pp[4];
#pragma unroll
            for (int qi = 0; qi < 4; qi++) {
                float pv = ss[(qbase + qi) * 17 + j];
                pp[qi] = pack2(pv, pv);
            }
            const ulonglong2* hrow = (const ulonglong2*)&hs[j * CC + cg * 16];
#pragma unroll
            for (int u = 0; u < 4; u++) {
                ulonglong2 hv = hrow[u];
#pragma unroll
                for (int qi = 0; qi < 4; qi++) {
                    fma2(acc[qi][2 * u + 0], pp[qi], hv.x);
                    fma2(acc[qi][2 * u + 1], pp[qi], hv.y);
                }
            }
        }
    }

    // ---- epilogue: normalize, add residual, store ----
    const int rowbase = b * NN + qt * 64;
#pragma unroll
    for (int qi = 0; qi < 4; qi++) {
        float inv = 1.0f / l[qi];
        size_t off = (size_t)(rowbase + qbase + qi) * CC + cg * 16;
        const float4* xr = (const float4*)&x[off];
        float4* outr = (float4*)&out[off];
#pragma unroll
        for (int u = 0; u < 4; u++) {
            float a0, a1, a2, a3;
            unpack2(acc[qi][2 * u + 0], a0, a1);
            unpack2(acc[qi][2 * u + 1], a2, a3);
            float4 xv = xr[u];
            float4 ov;
            ov.x = xv.x + a0 * inv;
            ov.y = xv.y + a1 * inv;
            ov.z = xv.z + a2 * inv;
            ov.w = xv.w + a3 * inv;
            outr[u] = ov;
        }
    }
}

// =====================================================================
extern "C" void kernel_launch(void* const* d_in, const int* in_sizes, int n_in,
                              void* d_out, int out_size)
{
    const float* x  = (const float*)d_in[0];
    const float* Wf = (const float*)d_in[1];
    const float* bf = (const float*)d_in[2];
    const float* Wg = (const float*)d_in[3];
    const float* bg = (const float*)d_in[4];
    const float* Wh = (const float*)d_in[5];
    const float* bh = (const float*)d_in[6];
    float* out = (float*)d_out;

    proj_kernel<<<BB * NN / 64, 256>>>(x, Wf, bf, Wg, bg, Wh, bh);
    flash_kernel<<<BB * NN / 64, 256>>>(x, out);
}

// round 5
// speedup vs baseline: 1.1559x; 1.1559x over previous
#include <cuda_runtime.h>
#include <cuda_bf16.h>
#include <cstdint>

// Shapes
#define BB 4
#define NN 4096          // H*W
#define CC 256
#define CK 32

// Scratch (device globals are the allowed scratch mechanism)
__device__ float d_F[BB * NN * CK];         // 2 MB
__device__ float d_G[BB * NN * CK];         // 2 MB
__device__ float d_H[(size_t)BB * NN * CC]; // 16 MB

// ---------------- packed f32x2 helpers ----------------
__device__ __forceinline__ unsigned long long pack2(float lo, float hi) {
    unsigned long long r;
    asm("mov.b64 %0, {%1, %2};" : "=l"(r) : "f"(lo), "f"(hi));
    return r;
}
__device__ __forceinline__ void unpack2(unsigned long long v, float& lo, float& hi) {
    asm("mov.b64 {%0, %1}, %2;" : "=f"(lo), "=f"(hi) : "l"(v));
}
__device__ __forceinline__ void fma2(unsigned long long& d, unsigned long long a,
                                     unsigned long long b) {
    asm("fma.rn.f32x2 %0, %1, %2, %3;" : "=l"(d) : "l"(a), "l"(b), "l"(d));
}
__device__ __forceinline__ void mul2(unsigned long long& d, unsigned long long a,
                                     unsigned long long b) {
    asm("mul.rn.f32x2 %0, %1, %2;" : "=l"(d) : "l"(a), "l"(b));
}

// =====================================================================
// Kernel 1: projections.  Per block: 64 pixels.  5 output chunks of 64
// (chunk 0 = f|g concatenated, chunks 1..4 = hh cols), K in 4 chunks of 64.
// =====================================================================
__global__ __launch_bounds__(256) void proj_kernel(
    const float* __restrict__ x,
    const float* __restrict__ Wf, const float* __restrict__ bfv,
    const float* __restrict__ Wg, const float* __restrict__ bgv,
    const float* __restrict__ Wh, const float* __restrict__ bhv)
{
    __shared__ float xs[64][64];   // 16 KB: [pixel][k]
    __shared__ float ws[64][64];   // 16 KB: [k][out]

    const int t = threadIdx.x;
    const int pix0 = blockIdx.x * 64;
    const int pg = t >> 4;   // pixel group (4 pixels)
    const int og = t & 15;   // out group (4 outputs)

    for (int oc = 0; oc < 5; oc++) {
        float acc[4][4];
#pragma unroll
        for (int i = 0; i < 4; i++)
#pragma unroll
            for (int j = 0; j < 4; j++) acc[i][j] = 0.f;

        for (int kc = 0; kc < 4; kc++) {
            __syncthreads();
            // load x tile [64 px][64 k]
            for (int i = t; i < 1024; i += 256) {
                int px = i >> 4;
                int kq = i & 15;
                *(float4*)&xs[px][kq * 4] =
                    *(const float4*)&x[(size_t)(pix0 + px) * CC + kc * 64 + kq * 4];
            }
            // load weight tile [64 k][64 out]
            for (int i = t; i < 4096; i += 256) {
                int k = i >> 6;
                int o = i & 63;
                int kg = kc * 64 + k;
                float v;
                if (oc == 0)
                    v = (o < 32) ? Wf[kg * CK + o] : Wg[kg * CK + (o - 32)];
                else
                    v = Wh[kg * CC + (oc - 1) * 64 + o];
                ws[k][o] = v;
            }
            __syncthreads();

#pragma unroll 8
            for (int k = 0; k < 64; k++) {
                float4 wv = *(const float4*)&ws[k][og * 4];
                float xv0 = xs[pg * 4 + 0][k];
                float xv1 = xs[pg * 4 + 1][k];
                float xv2 = xs[pg * 4 + 2][k];
                float xv3 = xs[pg * 4 + 3][k];
                acc[0][0] += xv0 * wv.x; acc[0][1] += xv0 * wv.y;
                acc[0][2] += xv0 * wv.z; acc[0][3] += xv0 * wv.w;
                acc[1][0] += xv1 * wv.x; acc[1][1] += xv1 * wv.y;
                acc[1][2] += xv1 * wv.z; acc[1][3] += xv1 * wv.w;
                acc[2][0] += xv2 * wv.x; acc[2][1] += xv2 * wv.y;
                acc[2][2] += xv2 * wv.z; acc[2][3] += xv2 * wv.w;
                acc[3][0] += xv3 * wv.x; acc[3][1] += xv3 * wv.y;
                acc[3][2] += xv3 * wv.z; acc[3][3] += xv3 * wv.w;
            }
        }

        // write back with bias
#pragma unroll
        for (int i = 0; i < 4; i++) {
            int px = pix0 + pg * 4 + i;
#pragma unroll
            for (int j = 0; j < 4; j++) {
                int o = og * 4 + j;
                float v = acc[i][j];
                if (oc == 0) {
                    if (o < 32) d_F[px * CK + o] = v + bfv[o];
                    else        d_G[px * CK + (o - 32)] = v + bgv[o - 32];
                } else {
                    int oo = (oc - 1) * 64 + o;
                    d_H[(size_t)px * CC + oo] = v + bhv[oo];
                }
            }
        }
    }
}

// =====================================================================
// Kernel 2: flash attention + residual.  STATIC smem < 48 KB.
// Block: 64 queries of one batch, 256 threads.
// Thread: 4 queries (qg = t>>4) x 16 channels (cg = t&15).
//
// hh tile stored INTERLEAVED to kill the 8-way bank conflict:
//   row j, dest float4 index dd = u*16 + cg  holds source channels
//   ch = cg*16 + u*4 .. +3.   (src float4 k = (dd&15)*4 + (dd>>4))
// PV reader (thread cg, sub-chunk u) loads float4 at [j*64 + u*16 + cg]:
//   16 lanes x 16B contiguous 256B -> conflict-free (qg halves broadcast).
// =====================================================================
#define JT 16

__global__ __launch_bounds__(256, 2) void flash_kernel(
    const float* __restrict__ x, float* __restrict__ out)
{
    __shared__ float hs[JT * CC];     // 16 KB  hh tile, interleaved layout
    __shared__ float fs[JT * 36];     // 2.25KB f tile padded [16][36]
    __shared__ float gs[64 * CK];     // 8 KB   g tile [64][32]
    __shared__ float ss[64 * 17];     // 4.25KB p tile padded [64][17]

    const int t = threadIdx.x;
    const int b = blockIdx.x >> 6;
    const int qt = blockIdx.x & 63;
    const int qg = t >> 4;      // 0..15
    const int cg = t & 15;      // 0..15
    const int qbase = qg * 4;

    const float* Fb = d_F + (size_t)b * NN * CK;
    const float* Hb = d_H + (size_t)b * NN * CC;
    const float* Gb = d_G + ((size_t)b * NN + qt * 64) * CK;

    // load g tile (64 x 32) into smem
    for (int i = t; i < 64 * CK / 4; i += 256)
        ((float4*)gs)[i] = ((const float4*)Gb)[i];

    unsigned long long acc[4][8];
#pragma unroll
    for (int qi = 0; qi < 4; qi++)
#pragma unroll
        for (int u = 0; u < 8; u++) acc[qi][u] = 0ull;

    float m[4], l[4];
#pragma unroll
    for (int qi = 0; qi < 4; qi++) { m[qi] = -1e30f; l[qi] = 0.f; }

    for (int j0 = 0; j0 < NN; j0 += JT) {
        __syncthreads();
        // f tile [16][32] -> fs padded [16][36]
        if (t < 128) {
            int r = t >> 3;          // 0..15
            int c4 = t & 7;          // 0..7
            float4 v = *(const float4*)&Fb[(size_t)(j0 + r) * CK + c4 * 4];
            *(float4*)&fs[r * 36 + c4 * 4] = v;
        }
        // hh tile [16][256] = 1024 float4, permuted gather -> linear store
        {
            const float4* src = (const float4*)&Hb[(size_t)j0 * CC];
            float4* dst = (float4*)hs;
#pragma unroll
            for (int ii = 0; ii < 4; ii++) {
                int d = t + 256 * ii;
                int jr = d >> 6;         // row 0..15
                int dd = d & 63;         // dest float4 within row
                int k = ((dd & 15) << 2) | (dd >> 4);  // source float4
                dst[(jr << 6) + dd] = src[(jr << 6) + k];
            }
        }
        __syncthreads();

        // ---- scores: thread computes s[q][cg] for its 4 q ----
        float sv[4];
#pragma unroll
        for (int qi = 0; qi < 4; qi++) sv[qi] = 0.f;
#pragma unroll
        for (int k = 0; k < CK; k += 4) {
            float4 f0 = *(const float4*)&fs[cg * 36 + k];
#pragma unroll
            for (int qi = 0; qi < 4; qi++) {
                float4 gq = *(const float4*)&gs[(qbase + qi) * CK + k];
                sv[qi] += gq.x * f0.x + gq.y * f0.y + gq.z * f0.z + gq.w * f0.w;
            }
        }

        // ---- online softmax update (reductions over 16-lane qg group) ----
#pragma unroll
        for (int qi = 0; qi < 4; qi++) {
            float v = sv[qi];
#pragma unroll
            for (int o = 1; o < 16; o <<= 1)
                v = fmaxf(v, __shfl_xor_sync(0xffffffffu, v, o));
            float mnew = fmaxf(m[qi], v);
            float scale = __expf(m[qi] - mnew);
            float p0 = __expf(sv[qi] - mnew);
            float lsum = p0;
#pragma unroll
            for (int o = 1; o < 16; o <<= 1)
                lsum += __shfl_xor_sync(0xffffffffu, lsum, o);
            l[qi] = l[qi] * scale + lsum;
            m[qi] = mnew;
            ss[(qbase + qi) * 17 + cg] = p0;
            unsigned long long s2 = pack2(scale, scale);
#pragma unroll
            for (int u = 0; u < 8; u++) mul2(acc[qi][u], acc[qi][u], s2);
        }
        __syncwarp();

        // ---- PV: o += p * hh, packed f32x2, conflict-free h loads ----
#pragma unroll 2
        for (int j = 0; j < JT; j++) {
            unsigned long long pp[4];
#pragma unroll
            for (int qi = 0; qi < 4; qi++) {
                float pv = ss[(qbase + qi) * 17 + j];
                pp[qi] = pack2(pv, pv);
            }
            const ulonglong2* hrow = (const ulonglong2*)&hs[j * CC];
#pragma unroll
            for (int u = 0; u < 4; u++) {
                ulonglong2 hv = hrow[u * 16 + cg];   // contiguous across lanes
#pragma unroll
                for (int qi = 0; qi < 4; qi++) {
                    fma2(acc[qi][2 * u + 0], pp[qi], hv.x);
                    fma2(acc[qi][2 * u + 1], pp[qi], hv.y);
                }
            }
        }
    }

    // ---- epilogue: normalize, add residual, store ----
    // acc[qi][2u+0] holds channels cg*16+u*4+{0,1}; [2u+1] -> +{2,3}
    const int rowbase = b * NN + qt * 64;
#pragma unroll
    for (int qi = 0; qi < 4; qi++) {
        float inv = 1.0f / l[qi];
        size_t off = (size_t)(rowbase + qbase + qi) * CC + cg * 16;
        const float4* xr = (const float4*)&x[off];
        float4* outr = (float4*)&out[off];
#pragma unroll
        for (int u = 0; u < 4; u++) {
            float a0, a1, a2, a3;
            unpack2(acc[qi][2 * u + 0], a0, a1);
            unpack2(acc[qi][2 * u + 1], a2, a3);
            float4 xv = xr[u];
            float4 ov;
            ov.x = xv.x + a0 * inv;
            ov.y = xv.y + a1 * inv;
            ov.z = xv.z + a2 * inv;
            ov.w = xv.w + a3 * inv;
            outr[u] = ov;
        }
    }
}

// =====================================================================
extern "C" void kernel_launch(void* const* d_in, const int* in_sizes, int n_in,
                              void* d_out, int out_size)
{
    const float* x  = (const float*)d_in[0];
    const float* Wf = (const float*)d_in[1];
    const float* bf = (const float*)d_in[2];
    const float* Wg = (const float*)d_in[3];
    const float* bg = (const float*)d_in[4];
    const float* Wh = (const float*)d_in[5];
    const float* bh = (const float*)d_in[6];
    float* out = (float*)d_out;

    proj_kernel<<<BB * NN / 64, 256>>>(x, Wf, bf, Wg, bg, Wh, bh);
    flash_kernel<<<BB * NN / 64, 256>>>(x, out);
}

// round 6
// speedup vs baseline: 1.3627x; 1.1789x over previous
#include <cuda_runtime.h>
#include <cuda_bf16.h>
#include <cstdint>

// Shapes
#define BB 4
#define NN 4096          // H*W
#define CC 256
#define CK 32

// Scratch (device globals are the allowed scratch mechanism)
__device__ float d_F[BB * NN * CK];         // 2 MB
__device__ float d_G[BB * NN * CK];         // 2 MB
__device__ float d_H[(size_t)BB * NN * CC]; // 16 MB

// ---------------- packed f32x2 helpers ----------------
__device__ __forceinline__ unsigned long long pack2(float lo, float hi) {
    unsigned long long r;
    asm("mov.b64 %0, {%1, %2};" : "=l"(r) : "f"(lo), "f"(hi));
    return r;
}
__device__ __forceinline__ void unpack2(unsigned long long v, float& lo, float& hi) {
    asm("mov.b64 {%0, %1}, %2;" : "=f"(lo), "=f"(hi) : "l"(v));
}
__device__ __forceinline__ void fma2(unsigned long long& d, unsigned long long a,
                                     unsigned long long b) {
    asm("fma.rn.f32x2 %0, %1, %2, %3;" : "=l"(d) : "l"(a), "l"(b), "l"(d));
}
__device__ __forceinline__ void mul2(unsigned long long& d, unsigned long long a,
                                     unsigned long long b) {
    asm("mul.rn.f32x2 %0, %1, %2;" : "=l"(d) : "l"(a), "l"(b));
}

// =====================================================================
// Kernel 1: projections (unchanged).
// =====================================================================
__global__ __launch_bounds__(256) void proj_kernel(
    const float* __restrict__ x,
    const float* __restrict__ Wf, const float* __restrict__ bfv,
    const float* __restrict__ Wg, const float* __restrict__ bgv,
    const float* __restrict__ Wh, const float* __restrict__ bhv)
{
    __shared__ float xs[64][64];
    __shared__ float ws[64][64];

    const int t = threadIdx.x;
    const int pix0 = blockIdx.x * 64;
    const int pg = t >> 4;
    const int og = t & 15;

    for (int oc = 0; oc < 5; oc++) {
        float acc[4][4];
#pragma unroll
        for (int i = 0; i < 4; i++)
#pragma unroll
            for (int j = 0; j < 4; j++) acc[i][j] = 0.f;

        for (int kc = 0; kc < 4; kc++) {
            __syncthreads();
            for (int i = t; i < 1024; i += 256) {
                int px = i >> 4;
                int kq = i & 15;
                *(float4*)&xs[px][kq * 4] =
                    *(const float4*)&x[(size_t)(pix0 + px) * CC + kc * 64 + kq * 4];
            }
            for (int i = t; i < 4096; i += 256) {
                int k = i >> 6;
                int o = i & 63;
                int kg = kc * 64 + k;
                float v;
                if (oc == 0)
                    v = (o < 32) ? Wf[kg * CK + o] : Wg[kg * CK + (o - 32)];
                else
                    v = Wh[kg * CC + (oc - 1) * 64 + o];
                ws[k][o] = v;
            }
            __syncthreads();

#pragma unroll 8
            for (int k = 0; k < 64; k++) {
                float4 wv = *(const float4*)&ws[k][og * 4];
                float xv0 = xs[pg * 4 + 0][k];
                float xv1 = xs[pg * 4 + 1][k];
                float xv2 = xs[pg * 4 + 2][k];
                float xv3 = xs[pg * 4 + 3][k];
                acc[0][0] += xv0 * wv.x; acc[0][1] += xv0 * wv.y;
                acc[0][2] += xv0 * wv.z; acc[0][3] += xv0 * wv.w;
                acc[1][0] += xv1 * wv.x; acc[1][1] += xv1 * wv.y;
                acc[1][2] += xv1 * wv.z; acc[1][3] += xv1 * wv.w;
                acc[2][0] += xv2 * wv.x; acc[2][1] += xv2 * wv.y;
                acc[2][2] += xv2 * wv.z; acc[2][3] += xv2 * wv.w;
                acc[3][0] += xv3 * wv.x; acc[3][1] += xv3 * wv.y;
                acc[3][2] += xv3 * wv.z; acc[3][3] += xv3 * wv.w;
            }
        }

#pragma unroll
        for (int i = 0; i < 4; i++) {
            int px = pix0 + pg * 4 + i;
#pragma unroll
            for (int j = 0; j < 4; j++) {
                int o = og * 4 + j;
                float v = acc[i][j];
                if (oc == 0) {
                    if (o < 32) d_F[px * CK + o] = v + bfv[o];
                    else        d_G[px * CK + (o - 32)] = v + bgv[o - 32];
                } else {
                    int oo = (oc - 1) * 64 + o;
                    d_H[(size_t)px * CC + oo] = v + bhv[oo];
                }
            }
        }
    }
}

// =====================================================================
// Kernel 2: flash attention + residual.
// Score phase mapping: thread (qg=t>>4 -> 4 q, cg=t&15 -> j index).
// PV phase mapping:    warp wid -> 8 q (shared by warp), lane -> 8 ch.
//   p read:  pp[j][wid*8..+7]   2x LDS.128 broadcast
//   h read:  half-row interleave, lane reads dest float4 {lane, 32+lane}
//            (dest dd <- src float4 ((dd&31)<<1)|(dd>>5))  conflict-free
// =====================================================================
#define JT 16

__global__ __launch_bounds__(256, 2) void flash_kernel(
    const float* __restrict__ x, float* __restrict__ out)
{
    __shared__ float hs[JT * CC];     // 16 KB  hh tile, half-row interleaved
    __shared__ float fs[JT * 36];     // f tile padded [16][36]
    __shared__ float gs[64 * CK];     // g tile [64][32]
    __shared__ float pp[JT * 72];     // p tile [j][q] padded
    __shared__ float sc[64];          // per-q scale (then 1/l)

    const int t = threadIdx.x;
    const int b = blockIdx.x >> 6;
    const int qt = blockIdx.x & 63;
    // score mapping
    const int qg = t >> 4;      // 0..15
    const int cg = t & 15;      // 0..15 (j index)
    const int qbase = qg * 4;
    // PV mapping
    const int wid = t >> 5;     // 0..7  (8 queries)
    const int lane = t & 31;    // 0..31 (8 channels)

    const float* Fb = d_F + (size_t)b * NN * CK;
    const float* Hb = d_H + (size_t)b * NN * CC;
    const float* Gb = d_G + ((size_t)b * NN + qt * 64) * CK;

    // load g tile (64 x 32)
    for (int i = t; i < 64 * CK / 4; i += 256)
        ((float4*)gs)[i] = ((const float4*)Gb)[i];

    unsigned long long acc[8][4];   // 8 q x 8 ch
#pragma unroll
    for (int qi = 0; qi < 8; qi++)
#pragma unroll
        for (int u = 0; u < 4; u++) acc[qi][u] = 0ull;

    float m[4], l[4];
#pragma unroll
    for (int qi = 0; qi < 4; qi++) { m[qi] = -1e30f; l[qi] = 0.f; }

    for (int j0 = 0; j0 < NN; j0 += JT) {
        __syncthreads();
        // f tile [16][32] -> fs padded [16][36]
        if (t < 128) {
            int r = t >> 3;
            int c4 = t & 7;
            float4 v = *(const float4*)&Fb[(size_t)(j0 + r) * CK + c4 * 4];
            *(float4*)&fs[r * 36 + c4 * 4] = v;
        }
        // hh tile: half-row interleave; dest dd <- src ((dd&31)<<1)|(dd>>5)
        {
            const float4* src = (const float4*)&Hb[(size_t)j0 * CC];
            float4* dst = (float4*)hs;
#pragma unroll
            for (int ii = 0; ii < 4; ii++) {
                int d = t + 256 * ii;
                int jr = d >> 6;
                int dd = d & 63;
                int k = ((dd & 31) << 1) | (dd >> 5);
                dst[(jr << 6) + dd] = src[(jr << 6) + k];
            }
        }
        __syncthreads();

        // ---- scores: thread computes s[qbase+qi][j=cg] ----
        float sv[4];
#pragma unroll
        for (int qi = 0; qi < 4; qi++) sv[qi] = 0.f;
#pragma unroll
        for (int k = 0; k < CK; k += 4) {
            float4 f0 = *(const float4*)&fs[cg * 36 + k];
#pragma unroll
            for (int qi = 0; qi < 4; qi++) {
                float4 gq = *(const float4*)&gs[(qbase + qi) * CK + k];
                sv[qi] += gq.x * f0.x + gq.y * f0.y + gq.z * f0.z + gq.w * f0.w;
            }
        }

        // ---- online softmax (reduce over 16 cg lanes = 16 j) ----
#pragma unroll
        for (int qi = 0; qi < 4; qi++) {
            float v = sv[qi];
#pragma unroll
            for (int o = 1; o < 16; o <<= 1)
                v = fmaxf(v, __shfl_xor_sync(0xffffffffu, v, o));
            float mnew = fmaxf(m[qi], v);
            float scale = __expf(m[qi] - mnew);
            float p0 = __expf(sv[qi] - mnew);
            float lsum = p0;
#pragma unroll
            for (int o = 1; o < 16; o <<= 1)
                lsum += __shfl_xor_sync(0xffffffffu, lsum, o);
            l[qi] = l[qi] * scale + lsum;
            m[qi] = mnew;
            pp[cg * 72 + qbase + qi] = p0;
            if (cg == 0) sc[qbase + qi] = scale;
        }
        __syncthreads();

        // ---- PV rescale (per-warp 8 q) ----
        {
            float4 s0 = *(const float4*)&sc[wid * 8];
            float4 s1 = *(const float4*)&sc[wid * 8 + 4];
            float scs[8] = {s0.x, s0.y, s0.z, s0.w, s1.x, s1.y, s1.z, s1.w};
#pragma unroll
            for (int qi = 0; qi < 8; qi++) {
                unsigned long long s2 = pack2(scs[qi], scs[qi]);
#pragma unroll
                for (int u = 0; u < 4; u++) mul2(acc[qi][u], acc[qi][u], s2);
            }
        }

        // ---- PV: o += p * hh ----
#pragma unroll 4
        for (int j = 0; j < JT; j++) {
            const float* ppr = &pp[j * 72 + wid * 8];
            float4 pA = *(const float4*)ppr;
            float4 pB = *(const float4*)(ppr + 4);
            const ulonglong2* hrow = (const ulonglong2*)&hs[j * CC];
            ulonglong2 h0 = hrow[lane];        // channels 8l..8l+3
            ulonglong2 h1 = hrow[32 + lane];   // channels 8l+4..8l+7
            float pq[8] = {pA.x, pA.y, pA.z, pA.w, pB.x, pB.y, pB.z, pB.w};
#pragma unroll
            for (int qi = 0; qi < 8; qi++) {
                unsigned long long pv = pack2(pq[qi], pq[qi]);
                fma2(acc[qi][0], pv, h0.x);
                fma2(acc[qi][1], pv, h0.y);
                fma2(acc[qi][2], pv, h1.x);
                fma2(acc[qi][3], pv, h1.y);
            }
        }
    }

    // ---- publish 1/l per q, then epilogue under PV mapping ----
    __syncthreads();
    if (cg == 0) {
#pragma unroll
        for (int qi = 0; qi < 4; qi++) sc[qbase + qi] = 1.0f / l[qi];
    }
    __syncthreads();

    {
        float4 l0 = *(const float4*)&sc[wid * 8];
        float4 l1 = *(const float4*)&sc[wid * 8 + 4];
        float linv[8] = {l0.x, l0.y, l0.z, l0.w, l1.x, l1.y, l1.z, l1.w};
        const int rowbase = b * NN + qt * 64 + wid * 8;
#pragma unroll
        for (int qi = 0; qi < 8; qi++) {
            size_t off = (size_t)(rowbase + qi) * CC + lane * 8;
            const float4* xr = (const float4*)&x[off];
            float4* outr = (float4*)&out[off];
            float a0, a1, a2, a3, a4, a5, a6, a7;
            unpack2(acc[qi][0], a0, a1);
            unpack2(acc[qi][1], a2, a3);
            unpack2(acc[qi][2], a4, a5);
            unpack2(acc[qi][3], a6, a7);
            float4 x0 = xr[0], x1 = xr[1];
            float4 o0, o1;
            o0.x = x0.x + a0 * linv[qi];
            o0.y = x0.y + a1 * linv[qi];
            o0.z = x0.z + a2 * linv[qi];
            o0.w = x0.w + a3 * linv[qi];
            o1.x = x1.x + a4 * linv[qi];
            o1.y = x1.y + a5 * linv[qi];
            o1.z = x1.z + a6 * linv[qi];
            o1.w = x1.w + a7 * linv[qi];
            outr[0] = o0;
            outr[1] = o1;
        }
    }
}

// =====================================================================
extern "C" void kernel_launch(void* const* d_in, const int* in_sizes, int n_in,
                              void* d_out, int out_size)
{
    const float* x  = (const float*)d_in[0];
    const float* Wf = (const float*)d_in[1];
    const float* bf = (const float*)d_in[2];
    const float* Wg = (const float*)d_in[3];
    const float* bg = (const float*)d_in[4];
    const float* Wh = (const float*)d_in[5];
    const float* bh = (const float*)d_in[6];
    float* out = (float*)d_out;

    proj_kernel<<<BB * NN / 64, 256>>>(x, Wf, bf, Wg, bg, Wh, bh);
    flash_kernel<<<BB * NN / 64, 256>>>(x, out);
}

// round 8
// speedup vs baseline: 4.9779x; 3.6530x over previous
#include <cuda_runtime.h>
#include <cuda_bf16.h>
#include <cstdint>

#define BB 4
#define NN 4096
#define CC 256
#define CK 32

// bf16 hi/lo split scratch (device globals = legal scratch)
__device__ __nv_bfloat16 d_Fhi[BB * NN * CK], d_Flo[BB * NN * CK];
__device__ __nv_bfloat16 d_Ghi[BB * NN * CK], d_Glo[BB * NN * CK];
__device__ __nv_bfloat16 d_Hhi[(size_t)BB * NN * CC], d_Hlo[(size_t)BB * NN * CC];

// ------------------------- helpers -------------------------
__device__ __forceinline__ uint32_t smem_u32(const void* p) {
    uint32_t a;
    asm("{ .reg .u64 t; cvta.to.shared.u64 t, %1; cvt.u32.u64 %0, t; }" : "=r"(a) : "l"(p));
    return a;
}
__device__ __forceinline__ void ldsm4(uint32_t* r, uint32_t a) {
    asm volatile("ldmatrix.sync.aligned.m8n8.x4.shared.b16 {%0,%1,%2,%3}, [%4];"
        : "=r"(r[0]), "=r"(r[1]), "=r"(r[2]), "=r"(r[3]) : "r"(a));
}
__device__ __forceinline__ void ldsm4t(uint32_t* r, uint32_t a) {
    asm volatile("ldmatrix.sync.aligned.m8n8.x4.trans.shared.b16 {%0,%1,%2,%3}, [%4];"
        : "=r"(r[0]), "=r"(r[1]), "=r"(r[2]), "=r"(r[3]) : "r"(a));
}
__device__ __forceinline__ void mma_bf16(float* d, const uint32_t* a, uint32_t b0, uint32_t b1) {
    asm volatile("mma.sync.aligned.m16n8k16.row.col.f32.bf16.bf16.f32 "
        "{%0,%1,%2,%3}, {%4,%5,%6,%7}, {%8,%9}, {%0,%1,%2,%3};"
        : "+f"(d[0]), "+f"(d[1]), "+f"(d[2]), "+f"(d[3])
        : "r"(a[0]), "r"(a[1]), "r"(a[2]), "r"(a[3]), "r"(b0), "r"(b1));
}
__device__ __forceinline__ void cpasync16(uint32_t saddr, const void* g) {
    asm volatile("cp.async.cg.shared.global [%0], [%1], 16;" :: "r"(saddr), "l"(g));
}
#define CP_COMMIT() asm volatile("cp.async.commit_group;")
#define CP_WAIT0()  asm volatile("cp.async.wait_group 0;" ::: "memory")
#define STS32(a, v) asm volatile("st.shared.b32 [%0], %1;" :: "r"(a), "r"(v) : "memory")

__device__ __forceinline__ void bsplit(float v, __nv_bfloat16& hi, __nv_bfloat16& lo) {
    hi = __float2bfloat16(v);
    lo = __float2bfloat16(v - __bfloat162float(hi));
}
__device__ __forceinline__ uint32_t pkbf(float a, float b) {
    return ((uint32_t)__bfloat16_as_ushort(__float2bfloat16(b)) << 16) |
           (uint32_t)__bfloat16_as_ushort(__float2bfloat16(a));
}

// smem layout (bytes): pitches G/P/F=80, H=528
#define OFF_GHI 0
#define OFF_GLO 5120
#define OFF_PHI 10240
#define OFF_PLO 15360
#define OFF_LRED 20480
#define OFF_F 20736          // + buf*5120 + hl*2560
#define OFF_H 30976          // + buf*33792 + hl*16896
#define SMEM3 98560

// =====================================================================
// Kernel 1: projections -> bf16 hi/lo splits
// =====================================================================
__global__ __launch_bounds__(256) void proj_kernel(
    const float* __restrict__ x,
    const float* __restrict__ Wf, const float* __restrict__ bfv,
    const float* __restrict__ Wg, const float* __restrict__ bgv,
    const float* __restrict__ Wh, const float* __restrict__ bhv)
{
    __shared__ float xs[64][64];
    __shared__ float ws[64][64];

    const int t = threadIdx.x;
    const int pix0 = blockIdx.x * 64;
    const int pg = t >> 4;
    const int og = t & 15;

    for (int oc = 0; oc < 5; oc++) {
        float acc[4][4];
#pragma unroll
        for (int i = 0; i < 4; i++)
#pragma unroll
            for (int j = 0; j < 4; j++) acc[i][j] = 0.f;

        for (int kc = 0; kc < 4; kc++) {
            __syncthreads();
            for (int i = t; i < 1024; i += 256) {
                int px = i >> 4;
                int kq = i & 15;
                *(float4*)&xs[px][kq * 4] =
                    *(const float4*)&x[(size_t)(pix0 + px) * CC + kc * 64 + kq * 4];
            }
            for (int i = t; i < 4096; i += 256) {
                int k = i >> 6;
                int o = i & 63;
                int kg = kc * 64 + k;
                float v;
                if (oc == 0)
                    v = (o < 32) ? Wf[kg * CK + o] : Wg[kg * CK + (o - 32)];
                else
                    v = Wh[kg * CC + (oc - 1) * 64 + o];
                ws[k][o] = v;
            }
            __syncthreads();

#pragma unroll 8
            for (int k = 0; k < 64; k++) {
                float4 wv = *(const float4*)&ws[k][og * 4];
                float xv0 = xs[pg * 4 + 0][k];
                float xv1 = xs[pg * 4 + 1][k];
                float xv2 = xs[pg * 4 + 2][k];
                float xv3 = xs[pg * 4 + 3][k];
                acc[0][0] += xv0 * wv.x; acc[0][1] += xv0 * wv.y;
                acc[0][2] += xv0 * wv.z; acc[0][3] += xv0 * wv.w;
                acc[1][0] += xv1 * wv.x; acc[1][1] += xv1 * wv.y;
                acc[1][2] += xv1 * wv.z; acc[1][3] += xv1 * wv.w;
                acc[2][0] += xv2 * wv.x; acc[2][1] += xv2 * wv.y;
                acc[2][2] += xv2 * wv.z; acc[2][3] += xv2 * wv.w;
                acc[3][0] += xv3 * wv.x; acc[3][1] += xv3 * wv.y;
                acc[3][2] += xv3 * wv.z; acc[3][3] += xv3 * wv.w;
            }
        }

#pragma unroll
        for (int i = 0; i < 4; i++) {
            int px = pix0 + pg * 4 + i;
#pragma unroll
            for (int j = 0; j < 4; j++) {
                int o = og * 4 + j;
                __nv_bfloat16 hi, lo;
                if (oc == 0) {
                    if (o < 32) {
                        bsplit(acc[i][j] + bfv[o], hi, lo);
                        d_Fhi[px * CK + o] = hi; d_Flo[px * CK + o] = lo;
                    } else {
                        bsplit(acc[i][j] + bgv[o - 32], hi, lo);
                        d_Ghi[px * CK + o - 32] = hi; d_Glo[px * CK + o - 32] = lo;
                    }
                } else {
                    int oo = (oc - 1) * 64 + o;
                    bsplit(acc[i][j] + bhv[oo], hi, lo);
                    d_Hhi[(size_t)px * CC + oo] = hi; d_Hlo[(size_t)px * CC + oo] = lo;
                }
            }
        }
    }
}

// =====================================================================
// tile loader: cp.async H (hi/lo) + F (hi/lo) for one 32-j tile
// =====================================================================
__device__ __forceinline__ void load_tile(uint32_t sb, int buf, size_t bpix, int j0, int t)
{
    uint32_t hb = sb + OFF_H + buf * 33792;
#pragma unroll
    for (int i = 0; i < 4; i++) {
        int id = t + 256 * i;
        int r = id >> 5, c = id & 31;
        uint32_t doff = (uint32_t)r * 528 + c * 16;
        cpasync16(hb + doff,         d_Hhi + (bpix + j0 + r) * CC + c * 8);
        cpasync16(hb + 16896 + doff, d_Hlo + (bpix + j0 + r) * CC + c * 8);
    }
    {
        int hl = t >> 7, r = (t >> 2) & 31, c = t & 3;
        const __nv_bfloat16* s = (hl ? d_Flo : d_Fhi) + (bpix + j0 + r) * CK + c * 8;
        cpasync16(sb + OFF_F + buf * 5120 + hl * 2560 + (uint32_t)r * 80 + c * 16, s);
    }
}

// =====================================================================
// Kernel 2: mma.sync flash attention. CTA = 64 q, 8 warps, JT=32, 128 tiles.
// No max-subtraction (logits bounded ~34). O in register fp32 frags.
// QK: warp w -> (16q block w&3) x (16j half w>>2). PV: warp w -> 32 ch.
// =====================================================================
__global__ __launch_bounds__(256, 1) void flash3(
    const float* __restrict__ x, float* __restrict__ out)
{
    extern __shared__ char sm[];
    const uint32_t sb = smem_u32(sm);
    const int t = threadIdx.x;
    const int w = t >> 5, l = t & 31;
    const int b = blockIdx.x >> 6, qt = blockIdx.x & 63;
    const size_t bpix = (size_t)b * NN;
    const size_t qpix = bpix + qt * 64;
    const int sel = l >> 3;
    const int mt = w & 3, nh = w >> 2;
    const int cb = w * 32;

    // initial loads: G (persistent) + tile 0
    {
        int r = t >> 2, c = t & 3;
        cpasync16(sb + OFF_GHI + (uint32_t)r * 80 + c * 16, d_Ghi + (qpix + r) * CK + c * 8);
        cpasync16(sb + OFF_GLO + (uint32_t)r * 80 + c * 16, d_Glo + (qpix + r) * CK + c * 8);
    }
    load_tile(sb, 0, bpix, 0, t);
    CP_COMMIT();
    CP_WAIT0();
    __syncthreads();

    float* lred = (float*)(sm + OFF_LRED);
    if (t < 64) lred[t] = 0.f;

    // persistent G A-fragments (q rows mt*16..+15, k 0..31)
    uint32_t aGh[2][4], aGl[2][4];
#pragma unroll
    for (int ks = 0; ks < 2; ks++) {
        uint32_t roff = (uint32_t)(mt * 16 + (sel & 1) * 8 + (l & 7)) * 80 + ks * 32 + (sel >> 1) * 16;
        ldsm4(aGh[ks], sb + OFF_GHI + roff);
        ldsm4(aGl[ks], sb + OFF_GLO + roff);
    }

    float O[4][4][4];
#pragma unroll
    for (int i = 0; i < 4; i++)
#pragma unroll
        for (int j = 0; j < 4; j++)
#pragma unroll
            for (int k = 0; k < 4; k++) O[i][j][k] = 0.f;
    float lacc0 = 0.f, lacc1 = 0.f;

#pragma unroll 1
    for (int tile = 0; tile < 128; tile++) {
        const int buf = tile & 1;
        if (tile > 0) {
            CP_WAIT0();
            __syncthreads();
        }
        if (tile + 1 < 128) {
            load_tile(sb, buf ^ 1, bpix, (tile + 1) * 32, t);
            CP_COMMIT();
        }

        // ---- QK: S[16q x 16j] ----
        uint32_t bFh[2][4], bFl[2][4];
        uint32_t fbase = sb + OFF_F + buf * 5120;
#pragma unroll
        for (int t2 = 0; t2 < 2; t2++) {
            uint32_t roff = (uint32_t)(nh * 16 + t2 * 8 + (l & 7)) * 80 + sel * 16;
            ldsm4(bFh[t2], fbase + roff);
            ldsm4(bFl[t2], fbase + 2560 + roff);
        }
        float d[2][4] = {0.f, 0.f, 0.f, 0.f, 0.f, 0.f, 0.f, 0.f};
#pragma unroll
        for (int t2 = 0; t2 < 2; t2++)
#pragma unroll
            for (int ks = 0; ks < 2; ks++) {
                mma_bf16(d[t2], aGh[ks], bFh[t2][ks * 2], bFh[t2][ks * 2 + 1]);
                mma_bf16(d[t2], aGh[ks], bFl[t2][ks * 2], bFl[t2][ks * 2 + 1]);
                mma_bf16(d[t2], aGl[ks], bFh[t2][ks * 2], bFh[t2][ks * 2 + 1]);
            }

        // ---- exp + P (bf16 hi/lo) to smem ----
        {
            int r0 = mt * 16 + (l >> 2);
#pragma unroll
            for (int t2 = 0; t2 < 2; t2++) {
                float e0 = __expf(d[t2][0]), e1 = __expf(d[t2][1]);
                float e2 = __expf(d[t2][2]), e3 = __expf(d[t2][3]);
                lacc0 += e0 + e1;
                lacc1 += e2 + e3;
                uint32_t colb = (uint32_t)(nh * 16 + t2 * 8 + (l & 3) * 2) * 2;
                __nv_bfloat16 h0 = __float2bfloat16(e0), h1 = __float2bfloat16(e1);
                __nv_bfloat16 h2 = __float2bfloat16(e2), h3 = __float2bfloat16(e3);
                uint32_t hi01 = ((uint32_t)__bfloat16_as_ushort(h1) << 16) | __bfloat16_as_ushort(h0);
                uint32_t hi23 = ((uint32_t)__bfloat16_as_ushort(h3) << 16) | __bfloat16_as_ushort(h2);
                STS32(sb + OFF_PHI + (uint32_t)r0 * 80 + colb, hi01);
                STS32(sb + OFF_PHI + (uint32_t)(r0 + 8) * 80 + colb, hi23);
                STS32(sb + OFF_PLO + (uint32_t)r0 * 80 + colb,
                      pkbf(e0 - __bfloat162float(h0), e1 - __bfloat162float(h1)));
                STS32(sb + OFF_PLO + (uint32_t)(r0 + 8) * 80 + colb,
                      pkbf(e2 - __bfloat162float(h2), e3 - __bfloat162float(h3)));
            }
        }
        __syncthreads();

        // ---- PV: O[64q x 32ch] += P . H ----
        uint32_t bHh[2][2][4], bHl[2][2][4];
        uint32_t hb = sb + OFF_H + buf * 33792;
#pragma unroll
        for (int ks = 0; ks < 2; ks++)
#pragma unroll
            for (int ntp = 0; ntp < 2; ntp++) {
                uint32_t roff = (uint32_t)(ks * 16 + (sel & 1) * 8 + (l & 7)) * 528 +
                                cb * 2 + ntp * 32 + (sel >> 1) * 16;
                ldsm4t(bHh[ks][ntp], hb + roff);
                ldsm4t(bHl[ks][ntp], hb + 16896 + roff);
            }
#pragma unroll
        for (int m2 = 0; m2 < 4; m2++) {
            uint32_t aPh[2][4], aPl[2][4];
#pragma unroll
            for (int ks = 0; ks < 2; ks++) {
                uint32_t roff = (uint32_t)(m2 * 16 + (sel & 1) * 8 + (l & 7)) * 80 +
                                ks * 32 + (sel >> 1) * 16;
                ldsm4(aPh[ks], sb + OFF_PHI + roff);
                ldsm4(aPl[ks], sb + OFF_PLO + roff);
            }
#pragma unroll
            for (int nt = 0; nt < 4; nt++) {
                int ntp = nt >> 1, o2 = (nt & 1) * 2;
#pragma unroll
                for (int ks = 0; ks < 2; ks++) {
                    mma_bf16(O[m2][nt], aPh[ks], bHh[ks][ntp][o2], bHh[ks][ntp][o2 + 1]);
                    mma_bf16(O[m2][nt], aPh[ks], bHl[ks][ntp][o2], bHl[ks][ntp][o2 + 1]);
                    mma_bf16(O[m2][nt], aPl[ks], bHh[ks][ntp][o2], bHh[ks][ntp][o2 + 1]);
                }
            }
        }
    }

    // ---- l reduction: quad shuffle + cross-warp atomic ----
    lacc0 += __shfl_xor_sync(0xffffffffu, lacc0, 1);
    lacc0 += __shfl_xor_sync(0xffffffffu, lacc0, 2);
    lacc1 += __shfl_xor_sync(0xffffffffu, lacc1, 1);
    lacc1 += __shfl_xor_sync(0xffffffffu, lacc1, 2);
    if ((l & 3) == 0) {
        atomicAdd(&lred[mt * 16 + (l >> 2)], lacc0);
        atomicAdd(&lred[mt * 16 + (l >> 2) + 8], lacc1);
    }
    __syncthreads();

    // ---- epilogue: normalize + residual ----
#pragma unroll
    for (int m2 = 0; m2 < 4; m2++) {
        int r0 = m2 * 16 + (l >> 2), r1 = r0 + 8;
        float i0 = 1.0f / lred[r0], i1 = 1.0f / lred[r1];
#pragma unroll
        for (int nt = 0; nt < 4; nt++) {
            int col = cb + nt * 8 + (l & 3) * 2;
            size_t p0 = (qpix + r0) * CC + col;
            size_t p1 = (qpix + r1) * CC + col;
            float2 xv0 = *(const float2*)&x[p0];
            float2 xv1 = *(const float2*)&x[p1];
            float2 ov0, ov1;
            ov0.x = xv0.x + O[m2][nt][0] * i0;
            ov0.y = xv0.y + O[m2][nt][1] * i0;
            ov1.x = xv1.x + O[m2][nt][2] * i1;
            ov1.y = xv1.y + O[m2][nt][3] * i1;
            *(float2*)&out[p0] = ov0;
            *(float2*)&out[p1] = ov1;
        }
    }
}

// =====================================================================
extern "C" void kernel_launch(void* const* d_in, const int* in_sizes, int n_in,
                              void* d_out, int out_size)
{
    const float* x  = (const float*)d_in[0];
    const float* Wf = (const float*)d_in[1];
    const float* bf = (const float*)d_in[2];
    const float* Wg = (const float*)d_in[3];
    const float* bg = (const float*)d_in[4];
    const float* Wh = (const float*)d_in[5];
    const float* bh = (const float*)d_in[6];
    float* out = (float*)d_out;

    cudaFuncSetAttribute(flash3, cudaFuncAttributeMaxDynamicSharedMemorySize, SMEM3);

    proj_kernel<<<BB * NN / 64, 256>>>(x, Wf, bf, Wg, bg, Wh, bh);
    flash3<<<BB * NN / 64, 256, SMEM3>>>(x, out);
}

// round 9
// speedup vs baseline: 5.0409x; 1.0127x over previous
#include <cuda_runtime.h>
#include <cuda_bf16.h>
#include <cstdint>

#define BB 4
#define NN 4096
#define CC 256
#define CK 32

// bf16 hi/lo split scratch (device globals = legal scratch)
__device__ __nv_bfloat16 d_Fhi[BB * NN * CK], d_Flo[BB * NN * CK];
__device__ __nv_bfloat16 d_Ghi[BB * NN * CK], d_Glo[BB * NN * CK];
__device__ __nv_bfloat16 d_Hhi[(size_t)BB * NN * CC], d_Hlo[(size_t)BB * NN * CC];

// ------------------------- helpers -------------------------
__device__ __forceinline__ uint32_t smem_u32(const void* p) {
    uint32_t a;
    asm("{ .reg .u64 t; cvta.to.shared.u64 t, %1; cvt.u32.u64 %0, t; }" : "=r"(a) : "l"(p));
    return a;
}
__device__ __forceinline__ void ldsm4(uint32_t* r, uint32_t a) {
    asm volatile("ldmatrix.sync.aligned.m8n8.x4.shared.b16 {%0,%1,%2,%3}, [%4];"
        : "=r"(r[0]), "=r"(r[1]), "=r"(r[2]), "=r"(r[3]) : "r"(a));
}
__device__ __forceinline__ void ldsm4t(uint32_t* r, uint32_t a) {
    asm volatile("ldmatrix.sync.aligned.m8n8.x4.trans.shared.b16 {%0,%1,%2,%3}, [%4];"
        : "=r"(r[0]), "=r"(r[1]), "=r"(r[2]), "=r"(r[3]) : "r"(a));
}
__device__ __forceinline__ void mma_bf16(float* d, const uint32_t* a, uint32_t b0, uint32_t b1) {
    asm volatile("mma.sync.aligned.m16n8k16.row.col.f32.bf16.bf16.f32 "
        "{%0,%1,%2,%3}, {%4,%5,%6,%7}, {%8,%9}, {%0,%1,%2,%3};"
        : "+f"(d[0]), "+f"(d[1]), "+f"(d[2]), "+f"(d[3])
        : "r"(a[0]), "r"(a[1]), "r"(a[2]), "r"(a[3]), "r"(b0), "r"(b1));
}
__device__ __forceinline__ void cpasync16(uint32_t saddr, const void* g) {
    asm volatile("cp.async.cg.shared.global [%0], [%1], 16;" :: "r"(saddr), "l"(g));
}
#define CP_COMMIT() asm volatile("cp.async.commit_group;")
#define CP_WAIT0()  asm volatile("cp.async.wait_group 0;" ::: "memory")
#define STS32(a, v) asm volatile("st.shared.b32 [%0], %1;" :: "r"(a), "r"(v) : "memory")

__device__ __forceinline__ void bsplit(float v, __nv_bfloat16& hi, __nv_bfloat16& lo) {
    hi = __float2bfloat16(v);
    lo = __float2bfloat16(v - __bfloat162float(hi));
}
__device__ __forceinline__ uint32_t pkbf(float a, float b) {
    return ((uint32_t)__bfloat16_as_ushort(__float2bfloat16(b)) << 16) |
           (uint32_t)__bfloat16_as_ushort(__float2bfloat16(a));
}

// smem layout (bytes): pitches G/P/F=80, H=528
#define OFF_GHI 0
#define OFF_GLO 5120
#define OFF_PHI 10240
#define OFF_PLO 15360
#define OFF_LRED 20480
#define OFF_F 20736          // + buf*5120 + hl*2560
#define OFF_H 30976          // + buf*33792 + hl*16896
#define SMEM3 98560

// =====================================================================
// Kernel 1: projections -> bf16 hi/lo splits (unchanged)
// =====================================================================
__global__ __launch_bounds__(256) void proj_kernel(
    const float* __restrict__ x,
    const float* __restrict__ Wf, const float* __restrict__ bfv,
    const float* __restrict__ Wg, const float* __restrict__ bgv,
    const float* __restrict__ Wh, const float* __restrict__ bhv)
{
    __shared__ float xs[64][64];
    __shared__ float ws[64][64];

    const int t = threadIdx.x;
    const int pix0 = blockIdx.x * 64;
    const int pg = t >> 4;
    const int og = t & 15;

    for (int oc = 0; oc < 5; oc++) {
        float acc[4][4];
#pragma unroll
        for (int i = 0; i < 4; i++)
#pragma unroll
            for (int j = 0; j < 4; j++) acc[i][j] = 0.f;

        for (int kc = 0; kc < 4; kc++) {
            __syncthreads();
            for (int i = t; i < 1024; i += 256) {
                int px = i >> 4;
                int kq = i & 15;
                *(float4*)&xs[px][kq * 4] =
                    *(const float4*)&x[(size_t)(pix0 + px) * CC + kc * 64 + kq * 4];
            }
            for (int i = t; i < 4096; i += 256) {
                int k = i >> 6;
                int o = i & 63;
                int kg = kc * 64 + k;
                float v;
                if (oc == 0)
                    v = (o < 32) ? Wf[kg * CK + o] : Wg[kg * CK + (o - 32)];
                else
                    v = Wh[kg * CC + (oc - 1) * 64 + o];
                ws[k][o] = v;
            }
            __syncthreads();

#pragma unroll 8
            for (int k = 0; k < 64; k++) {
                float4 wv = *(const float4*)&ws[k][og * 4];
                float xv0 = xs[pg * 4 + 0][k];
                float xv1 = xs[pg * 4 + 1][k];
                float xv2 = xs[pg * 4 + 2][k];
                float xv3 = xs[pg * 4 + 3][k];
                acc[0][0] += xv0 * wv.x; acc[0][1] += xv0 * wv.y;
                acc[0][2] += xv0 * wv.z; acc[0][3] += xv0 * wv.w;
                acc[1][0] += xv1 * wv.x; acc[1][1] += xv1 * wv.y;
                acc[1][2] += xv1 * wv.z; acc[1][3] += xv1 * wv.w;
                acc[2][0] += xv2 * wv.x; acc[2][1] += xv2 * wv.y;
                acc[2][2] += xv2 * wv.z; acc[2][3] += xv2 * wv.w;
                acc[3][0] += xv3 * wv.x; acc[3][1] += xv3 * wv.y;
                acc[3][2] += xv3 * wv.z; acc[3][3] += xv3 * wv.w;
            }
        }

#pragma unroll
        for (int i = 0; i < 4; i++) {
            int px = pix0 + pg * 4 + i;
#pragma unroll
            for (int j = 0; j < 4; j++) {
                int o = og * 4 + j;
                __nv_bfloat16 hi, lo;
                if (oc == 0) {
                    if (o < 32) {
                        bsplit(acc[i][j] + bfv[o], hi, lo);
                        d_Fhi[px * CK + o] = hi; d_Flo[px * CK + o] = lo;
                    } else {
                        bsplit(acc[i][j] + bgv[o - 32], hi, lo);
                        d_Ghi[px * CK + o - 32] = hi; d_Glo[px * CK + o - 32] = lo;
                    }
                } else {
                    int oo = (oc - 1) * 64 + o;
                    bsplit(acc[i][j] + bhv[oo], hi, lo);
                    d_Hhi[(size_t)px * CC + oo] = hi; d_Hlo[(size_t)px * CC + oo] = lo;
                }
            }
        }
    }
}

// =====================================================================
// tile loader for 512 threads: cp.async H (hi/lo) + F (hi/lo), JT=32
// =====================================================================
__device__ __forceinline__ void load_tile(uint32_t sb, int buf, size_t bpix, int j0, int t)
{
    uint32_t hb = sb + OFF_H + buf * 33792;
#pragma unroll
    for (int i = 0; i < 4; i++) {
        int id = t + 512 * i;
        int hl = id >> 10, r = (id >> 5) & 31, c = id & 31;
        const __nv_bfloat16* s = (hl ? d_Hlo : d_Hhi) + (bpix + j0 + r) * CC + c * 8;
        cpasync16(hb + hl * 16896 + (uint32_t)r * 528 + c * 16, s);
    }
    if (t < 256) {
        int hl = t >> 7, r = (t >> 2) & 31, c = t & 3;
        const __nv_bfloat16* s = (hl ? d_Flo : d_Fhi) + (bpix + j0 + r) * CK + c * 8;
        cpasync16(sb + OFF_F + buf * 5120 + hl * 2560 + (uint32_t)r * 80 + c * 16, s);
    }
}

// =====================================================================
// Kernel 2: mma.sync flash. CTA = 64 q, 16 warps (512 thr), JT=32.
// QK: warp -> (16q mt=w&3) x (8j n8=w>>2).  PV: warp -> 16 ch (cb=w*16).
// No max-subtraction; O in register fp32 frags (32/thread).
// =====================================================================
__global__ __launch_bounds__(512, 1) void flash3(
    const float* __restrict__ x, float* __restrict__ out)
{
    extern __shared__ char sm[];
    const uint32_t sb = smem_u32(sm);
    const int t = threadIdx.x;
    const int w = t >> 5, l = t & 31;
    const int b = blockIdx.x >> 6, qt = blockIdx.x & 63;
    const size_t bpix = (size_t)b * NN;
    const size_t qpix = bpix + qt * 64;
    const int sel = l >> 3;
    const int mt = w & 3, n8 = w >> 2;
    const int cb = w * 16;

    // initial loads: G (persistent, 64x32 hi/lo) + tile 0
    {
        int hl = t >> 8, r = (t >> 2) & 63, c = t & 3;
        const __nv_bfloat16* s = (hl ? d_Glo : d_Ghi) + (qpix + r) * CK + c * 8;
        cpasync16(sb + (hl ? OFF_GLO : OFF_GHI) + (uint32_t)r * 80 + c * 16, s);
    }
    load_tile(sb, 0, bpix, 0, t);
    CP_COMMIT();
    CP_WAIT0();
    __syncthreads();

    float* lred = (float*)(sm + OFF_LRED);
    if (t < 64) lred[t] = 0.f;

    // persistent G A-fragments (q rows mt*16..+15, k 0..31)
    uint32_t aGh[2][4], aGl[2][4];
#pragma unroll
    for (int ks = 0; ks < 2; ks++) {
        uint32_t roff = (uint32_t)(mt * 16 + (sel & 1) * 8 + (l & 7)) * 80 + ks * 32 + (sel >> 1) * 16;
        ldsm4(aGh[ks], sb + OFF_GHI + roff);
        ldsm4(aGl[ks], sb + OFF_GLO + roff);
    }

    float O[4][2][4];
#pragma unroll
    for (int i = 0; i < 4; i++)
#pragma unroll
        for (int j = 0; j < 2; j++)
#pragma unroll
            for (int k = 0; k < 4; k++) O[i][j][k] = 0.f;
    float lacc0 = 0.f, lacc1 = 0.f;

#pragma unroll 1
    for (int tile = 0; tile < 128; tile++) {
        const int buf = tile & 1;
        if (tile > 0) {
            CP_WAIT0();
            __syncthreads();
        }
        if (tile + 1 < 128) {
            load_tile(sb, buf ^ 1, bpix, (tile + 1) * 32, t);
            CP_COMMIT();
        }

        // ---- QK: S[16q x 8j] per warp ----
        uint32_t bFh[4], bFl[4];
        {
            uint32_t fbase = sb + OFF_F + buf * 5120;
            uint32_t roff = (uint32_t)(n8 * 8 + (l & 7)) * 80 + sel * 16;
            ldsm4(bFh, fbase + roff);
            ldsm4(bFl, fbase + 2560 + roff);
        }
        float d[4] = {0.f, 0.f, 0.f, 0.f};
#pragma unroll
        for (int ks = 0; ks < 2; ks++) {
            mma_bf16(d, aGh[ks], bFh[ks * 2], bFh[ks * 2 + 1]);
            mma_bf16(d, aGh[ks], bFl[ks * 2], bFl[ks * 2 + 1]);
            mma_bf16(d, aGl[ks], bFh[ks * 2], bFh[ks * 2 + 1]);
        }

        // ---- exp + P (bf16 hi/lo) to smem ----
        {
            int r0 = mt * 16 + (l >> 2);
            float e0 = __expf(d[0]), e1 = __expf(d[1]);
            float e2 = __expf(d[2]), e3 = __expf(d[3]);
            lacc0 += e0 + e1;
            lacc1 += e2 + e3;
            uint32_t colb = (uint32_t)(n8 * 8 + (l & 3) * 2) * 2;
            __nv_bfloat16 h0 = __float2bfloat16(e0), h1 = __float2bfloat16(e1);
            __nv_bfloat16 h2 = __float2bfloat16(e2), h3 = __float2bfloat16(e3);
            uint32_t hi01 = ((uint32_t)__bfloat16_as_ushort(h1) << 16) | __bfloat16_as_ushort(h0);
            uint32_t hi23 = ((uint32_t)__bfloat16_as_ushort(h3) << 16) | __bfloat16_as_ushort(h2);
            STS32(sb + OFF_PHI + (uint32_t)r0 * 80 + colb, hi01);
            STS32(sb + OFF_PHI + (uint32_t)(r0 + 8) * 80 + colb, hi23);
            STS32(sb + OFF_PLO + (uint32_t)r0 * 80 + colb,
                  pkbf(e0 - __bfloat162float(h0), e1 - __bfloat162float(h1)));
            STS32(sb + OFF_PLO + (uint32_t)(r0 + 8) * 80 + colb,
                  pkbf(e2 - __bfloat162float(h2), e3 - __bfloat162float(h3)));
        }
        __syncthreads();

        // ---- PV: O[64q x 16ch] per warp += P . H ----
        uint32_t bHh[2][4], bHl[2][4];
        uint32_t hb = sb + OFF_H + buf * 33792;
#pragma unroll
        for (int ks = 0; ks < 2; ks++) {
            uint32_t roff = (uint32_t)(ks * 16 + (sel & 1) * 8 + (l & 7)) * 528 +
                            cb * 2 + (sel >> 1) * 16;
            ldsm4t(bHh[ks], hb + roff);
            ldsm4t(bHl[ks], hb + 16896 + roff);
        }
#pragma unroll
        for (int m2 = 0; m2 < 4; m2++) {
            uint32_t aPh[2][4], aPl[2][4];
#pragma unroll
            for (int ks = 0; ks < 2; ks++) {
                uint32_t roff = (uint32_t)(m2 * 16 + (sel & 1) * 8 + (l & 7)) * 80 +
                                ks * 32 + (sel >> 1) * 16;
                ldsm4(aPh[ks], sb + OFF_PHI + roff);
                ldsm4(aPl[ks], sb + OFF_PLO + roff);
            }
#pragma unroll
            for (int nt = 0; nt < 2; nt++) {
                int o2 = nt * 2;
#pragma unroll
                for (int ks = 0; ks < 2; ks++) {
                    mma_bf16(O[m2][nt], aPh[ks], bHh[ks][o2], bHh[ks][o2 + 1]);
                    mma_bf16(O[m2][nt], aPh[ks], bHl[ks][o2], bHl[ks][o2 + 1]);
                    mma_bf16(O[m2][nt], aPl[ks], bHh[ks][o2], bHh[ks][o2 + 1]);
                }
            }
        }
    }

    // ---- l reduction: quad shuffle + cross-warp atomic ----
    lacc0 += __shfl_xor_sync(0xffffffffu, lacc0, 1);
    lacc0 += __shfl_xor_sync(0xffffffffu, lacc0, 2);
    lacc1 += __shfl_xor_sync(0xffffffffu, lacc1, 1);
    lacc1 += __shfl_xor_sync(0xffffffffu, lacc1, 2);
    if ((l & 3) == 0) {
        atomicAdd(&lred[mt * 16 + (l >> 2)], lacc0);
        atomicAdd(&lred[mt * 16 + (l >> 2) + 8], lacc1);
    }
    __syncthreads();

    // ---- epilogue: normalize + residual ----
#pragma unroll
    for (int m2 = 0; m2 < 4; m2++) {
        int r0 = m2 * 16 + (l >> 2), r1 = r0 + 8;
        float i0 = 1.0f / lred[r0], i1 = 1.0f / lred[r1];
#pragma unroll
        for (int nt = 0; nt < 2; nt++) {
            int col = cb + nt * 8 + (l & 3) * 2;
            size_t p0 = (qpix + r0) * CC + col;
            size_t p1 = (qpix + r1) * CC + col;
            float2 xv0 = *(const float2*)&x[p0];
            float2 xv1 = *(const float2*)&x[p1];
            float2 ov0, ov1;
            ov0.x = xv0.x + O[m2][nt][0] * i0;
            ov0.y = xv0.y + O[m2][nt][1] * i0;
            ov1.x = xv1.x + O[m2][nt][2] * i1;
            ov1.y = xv1.y + O[m2][nt][3] * i1;
            *(float2*)&out[p0] = ov0;
            *(float2*)&out[p1] = ov1;
        }
    }
}

// =====================================================================
extern "C" void kernel_launch(void* const* d_in, const int* in_sizes, int n_in,
                              void* d_out, int out_size)
{
    const float* x  = (const float*)d_in[0];
    const float* Wf = (const float*)d_in[1];
    const float* bf = (const float*)d_in[2];
    const float* Wg = (const float*)d_in[3];
    const float* bg = (const float*)d_in[4];
    const float* Wh = (const float*)d_in[5];
    const float* bh = (const float*)d_in[6];
    float* out = (float*)d_out;

    cudaFuncSetAttribute(flash3, cudaFuncAttributeMaxDynamicSharedMemorySize, SMEM3);

    proj_kernel<<<BB * NN / 64, 256>>>(x, Wf, bf, Wg, bg, Wh, bh);
    flash3<<<BB * NN / 64, 512, SMEM3>>>(x, out);
}

// round 10
// speedup vs baseline: 5.2892x; 1.0493x over previous
#include <cuda_runtime.h>
#include <cuda_bf16.h>
#include <cstdint>

#define BB 4
#define NN 4096
#define CC 256
#define CK 32

// bf16 hi/lo split scratch (device globals = legal scratch)
__device__ __nv_bfloat16 d_Fhi[BB * NN * CK], d_Flo[BB * NN * CK];
__device__ __nv_bfloat16 d_Ghi[BB * NN * CK], d_Glo[BB * NN * CK];
__device__ __nv_bfloat16 d_Hhi[(size_t)BB * NN * CC], d_Hlo[(size_t)BB * NN * CC];

// ------------------------- helpers -------------------------
__device__ __forceinline__ uint32_t smem_u32(const void* p) {
    uint32_t a;
    asm("{ .reg .u64 t; cvta.to.shared.u64 t, %1; cvt.u32.u64 %0, t; }" : "=r"(a) : "l"(p));
    return a;
}
__device__ __forceinline__ void ldsm4(uint32_t* r, uint32_t a) {
    asm volatile("ldmatrix.sync.aligned.m8n8.x4.shared.b16 {%0,%1,%2,%3}, [%4];"
        : "=r"(r[0]), "=r"(r[1]), "=r"(r[2]), "=r"(r[3]) : "r"(a));
}
__device__ __forceinline__ void ldsm4t(uint32_t* r, uint32_t a) {
    asm volatile("ldmatrix.sync.aligned.m8n8.x4.trans.shared.b16 {%0,%1,%2,%3}, [%4];"
        : "=r"(r[0]), "=r"(r[1]), "=r"(r[2]), "=r"(r[3]) : "r"(a));
}
__device__ __forceinline__ void mma_bf16(float* d, const uint32_t* a, uint32_t b0, uint32_t b1) {
    asm volatile("mma.sync.aligned.m16n8k16.row.col.f32.bf16.bf16.f32 "
        "{%0,%1,%2,%3}, {%4,%5,%6,%7}, {%8,%9}, {%0,%1,%2,%3};"
        : "+f"(d[0]), "+f"(d[1]), "+f"(d[2]), "+f"(d[3])
        : "r"(a[0]), "r"(a[1]), "r"(a[2]), "r"(a[3]), "r"(b0), "r"(b1));
}
__device__ __forceinline__ void cpasync16(uint32_t saddr, const void* g) {
    asm volatile("cp.async.cg.shared.global [%0], [%1], 16;" :: "r"(saddr), "l"(g));
}
#define CP_COMMIT() asm volatile("cp.async.commit_group;")
#define CP_WAIT0()  asm volatile("cp.async.wait_group 0;" ::: "memory")
#define STS32(a, v) asm volatile("st.shared.b32 [%0], %1;" :: "r"(a), "r"(v) : "memory")

__device__ __forceinline__ void bsplit(float v, __nv_bfloat16& hi, __nv_bfloat16& lo) {
    hi = __float2bfloat16(v);
    lo = __float2bfloat16(v - __bfloat162float(hi));
}
__device__ __forceinline__ uint32_t pkbf(float a, float b) {
    return ((uint32_t)__bfloat16_as_ushort(__float2bfloat16(b)) << 16) |
           (uint32_t)__bfloat16_as_ushort(__float2bfloat16(a));
}

// smem layout (bytes): pitches G/P/F=80, H=528
#define OFF_G    0            // hi +0, lo +5120
#define OFF_P    10240        // + pbuf*10240; hi +0, lo +5120
#define OFF_LRED 30720
#define OFF_F    30976        // + fbuf*5120;  hi +0, lo +2560
#define OFF_H    46336        // + hbuf*33792; hi +0, lo +16896
#define SMEM3    147712

// =====================================================================
// Kernel 1: projections -> bf16 hi/lo splits (unchanged)
// =====================================================================
__global__ __launch_bounds__(256) void proj_kernel(
    const float* __restrict__ x,
    const float* __restrict__ Wf, const float* __restrict__ bfv,
    const float* __restrict__ Wg, const float* __restrict__ bgv,
    const float* __restrict__ Wh, const float* __restrict__ bhv)
{
    __shared__ float xs[64][64];
    __shared__ float ws[64][64];

    const int t = threadIdx.x;
    const int pix0 = blockIdx.x * 64;
    const int pg = t >> 4;
    const int og = t & 15;

    for (int oc = 0; oc < 5; oc++) {
        float acc[4][4];
#pragma unroll
        for (int i = 0; i < 4; i++)
#pragma unroll
            for (int j = 0; j < 4; j++) acc[i][j] = 0.f;

        for (int kc = 0; kc < 4; kc++) {
            __syncthreads();
            for (int i = t; i < 1024; i += 256) {
                int px = i >> 4;
                int kq = i & 15;
                *(float4*)&xs[px][kq * 4] =
                    *(const float4*)&x[(size_t)(pix0 + px) * CC + kc * 64 + kq * 4];
            }
            for (int i = t; i < 4096; i += 256) {
                int k = i >> 6;
                int o = i & 63;
                int kg = kc * 64 + k;
                float v;
                if (oc == 0)
                    v = (o < 32) ? Wf[kg * CK + o] : Wg[kg * CK + (o - 32)];
                else
                    v = Wh[kg * CC + (oc - 1) * 64 + o];
                ws[k][o] = v;
            }
            __syncthreads();

#pragma unroll 8
            for (int k = 0; k < 64; k++) {
                float4 wv = *(const float4*)&ws[k][og * 4];
                float xv0 = xs[pg * 4 + 0][k];
                float xv1 = xs[pg * 4 + 1][k];
                float xv2 = xs[pg * 4 + 2][k];
                float xv3 = xs[pg * 4 + 3][k];
                acc[0][0] += xv0 * wv.x; acc[0][1] += xv0 * wv.y;
                acc[0][2] += xv0 * wv.z; acc[0][3] += xv0 * wv.w;
                acc[1][0] += xv1 * wv.x; acc[1][1] += xv1 * wv.y;
                acc[1][2] += xv1 * wv.z; acc[1][3] += xv1 * wv.w;
                acc[2][0] += xv2 * wv.x; acc[2][1] += xv2 * wv.y;
                acc[2][2] += xv2 * wv.z; acc[2][3] += xv2 * wv.w;
                acc[3][0] += xv3 * wv.x; acc[3][1] += xv3 * wv.y;
                acc[3][2] += xv3 * wv.z; acc[3][3] += xv3 * wv.w;
            }
        }

#pragma unroll
        for (int i = 0; i < 4; i++) {
            int px = pix0 + pg * 4 + i;
#pragma unroll
            for (int j = 0; j < 4; j++) {
                int o = og * 4 + j;
                __nv_bfloat16 hi, lo;
                if (oc == 0) {
                    if (o < 32) {
                        bsplit(acc[i][j] + bfv[o], hi, lo);
                        d_Fhi[px * CK + o] = hi; d_Flo[px * CK + o] = lo;
                    } else {
                        bsplit(acc[i][j] + bgv[o - 32], hi, lo);
                        d_Ghi[px * CK + o - 32] = hi; d_Glo[px * CK + o - 32] = lo;
                    }
                } else {
                    int oo = (oc - 1) * 64 + o;
                    bsplit(acc[i][j] + bhv[oo], hi, lo);
                    d_Hhi[(size_t)px * CC + oo] = hi; d_Hlo[(size_t)px * CC + oo] = lo;
                }
            }
        }
    }
}

// =====================================================================
// tile loader (512 threads): cp.async H (hi/lo) + F (hi/lo), JT=32
// =====================================================================
__device__ __forceinline__ void load_tile(uint32_t sb, int buf, size_t bpix, int j0, int t)
{
    uint32_t hb = sb + OFF_H + buf * 33792;
#pragma unroll
    for (int i = 0; i < 4; i++) {
        int id = t + 512 * i;
        int hl = id >> 10, r = (id >> 5) & 31, c = id & 31;
        const __nv_bfloat16* s = (hl ? d_Hlo : d_Hhi) + (bpix + j0 + r) * CC + c * 8;
        cpasync16(hb + hl * 16896 + (uint32_t)r * 528 + c * 16, s);
    }
    if (t < 256) {
        int hl = t >> 7, r = (t >> 2) & 31, c = t & 3;
        const __nv_bfloat16* s = (hl ? d_Flo : d_Fhi) + (bpix + j0 + r) * CK + c * 8;
        cpasync16(sb + OFF_F + buf * 5120 + hl * 2560 + (uint32_t)r * 80 + c * 16, s);
    }
}

// =====================================================================
// Kernel 2: pipelined mma.sync flash. CTA = 64 q, 16 warps, JT=32.
// Schedule per iter t: wait(t+1) -> sync -> load(t+2) ->
//   QK(t+1) -> PV(t) -> exp(t+1)->STS P.  One sync per tile.
// P double-buffered, F/H triple-buffered.
// =====================================================================
__global__ __launch_bounds__(512, 1) void flash3(
    const float* __restrict__ x, float* __restrict__ out)
{
    extern __shared__ char sm[];
    const uint32_t sb = smem_u32(sm);
    const int t = threadIdx.x;
    const int w = t >> 5, l = t & 31;
    const int b = blockIdx.x >> 6, qt = blockIdx.x & 63;
    const size_t bpix = (size_t)b * NN;
    const size_t qpix = bpix + qt * 64;
    const int sel = l >> 3;
    const int mt = w & 3, n8 = w >> 2;
    const int cb = w * 16;

    // prologue: G (persistent) + tile 0
    {
        int hl = t >> 8, r = (t >> 2) & 63, c = t & 3;
        const __nv_bfloat16* s = (hl ? d_Glo : d_Ghi) + (qpix + r) * CK + c * 8;
        cpasync16(sb + OFF_G + hl * 5120 + (uint32_t)r * 80 + c * 16, s);
    }
    load_tile(sb, 0, bpix, 0, t);
    CP_COMMIT();
    CP_WAIT0();
    __syncthreads();

    float* lred = (float*)(sm + OFF_LRED);
    if (t < 64) lred[t] = 0.f;

    // persistent G A-fragments (q rows mt*16..+15, k 0..31)
    uint32_t aGh[2][4], aGl[2][4];
#pragma unroll
    for (int ks = 0; ks < 2; ks++) {
        uint32_t roff = (uint32_t)(mt * 16 + (sel & 1) * 8 + (l & 7)) * 80 + ks * 32 + (sel >> 1) * 16;
        ldsm4(aGh[ks], sb + OFF_G + roff);
        ldsm4(aGl[ks], sb + OFF_G + 5120 + roff);
    }

    // start tile-1 load
    load_tile(sb, 1, bpix, 32, t);
    CP_COMMIT();

    float O[4][2][4];
#pragma unroll
    for (int i = 0; i < 4; i++)
#pragma unroll
        for (int j = 0; j < 2; j++)
#pragma unroll
            for (int k = 0; k < 4; k++) O[i][j][k] = 0.f;
    float lacc0 = 0.f, lacc1 = 0.f;

    const uint32_t qk_roff = (uint32_t)(n8 * 8 + (l & 7)) * 80 + sel * 16;
    const uint32_t p_colb  = (uint32_t)(n8 * 8 + (l & 3) * 2) * 2;
    const int p_r0 = mt * 16 + (l >> 2);

    // QK(0) + exp -> P buf 0  (F buf 0 ready)
    {
        uint32_t bFh[4], bFl[4];
        ldsm4(bFh, sb + OFF_F + qk_roff);
        ldsm4(bFl, sb + OFF_F + 2560 + qk_roff);
        float d[4] = {0.f, 0.f, 0.f, 0.f};
#pragma unroll
        for (int ks = 0; ks < 2; ks++) {
            mma_bf16(d, aGh[ks], bFh[ks * 2], bFh[ks * 2 + 1]);
            mma_bf16(d, aGh[ks], bFl[ks * 2], bFl[ks * 2 + 1]);
            mma_bf16(d, aGl[ks], bFh[ks * 2], bFh[ks * 2 + 1]);
        }
        float e0 = __expf(d[0]), e1 = __expf(d[1]);
        float e2 = __expf(d[2]), e3 = __expf(d[3]);
        lacc0 += e0 + e1; lacc1 += e2 + e3;
        __nv_bfloat16 h0 = __float2bfloat16(e0), h1 = __float2bfloat16(e1);
        __nv_bfloat16 h2 = __float2bfloat16(e2), h3 = __float2bfloat16(e3);
        uint32_t pb = sb + OFF_P;
        STS32(pb + (uint32_t)p_r0 * 80 + p_colb,
              ((uint32_t)__bfloat16_as_ushort(h1) << 16) | __bfloat16_as_ushort(h0));
        STS32(pb + (uint32_t)(p_r0 + 8) * 80 + p_colb,
              ((uint32_t)__bfloat16_as_ushort(h3) << 16) | __bfloat16_as_ushort(h2));
        STS32(pb + 5120 + (uint32_t)p_r0 * 80 + p_colb,
              pkbf(e0 - __bfloat162float(h0), e1 - __bfloat162float(h1)));
        STS32(pb + 5120 + (uint32_t)(p_r0 + 8) * 80 + p_colb,
              pkbf(e2 - __bfloat162float(h2), e3 - __bfloat162float(h3)));
    }

    int cur = 0, nxt = 1, nx2 = 2;   // t%3, (t+1)%3, (t+2)%3

#pragma unroll 1
    for (int tile = 0; tile < 128; tile++) {
        CP_WAIT0();          // tile+1 data arrived (no-op on last iter)
        __syncthreads();     // P[tile&1] visible; F/H[tile+1] visible; PV(tile-1) done
        if (tile + 2 < 128) {
            load_tile(sb, nx2, bpix, (tile + 2) * 32, t);
            CP_COMMIT();
        }

        // ---- QK(tile+1): S[16q x 8j] per warp ----
        float d[4] = {0.f, 0.f, 0.f, 0.f};
        if (tile + 1 < 128) {
            uint32_t fb = sb + OFF_F + nxt * 5120;
            uint32_t bFh[4], bFl[4];
            ldsm4(bFh, fb + qk_roff);
            ldsm4(bFl, fb + 2560 + qk_roff);
#pragma unroll
            for (int ks = 0; ks < 2; ks++) {
                mma_bf16(d, aGh[ks], bFh[ks * 2], bFh[ks * 2 + 1]);
                mma_bf16(d, aGh[ks], bFl[ks * 2], bFl[ks * 2 + 1]);
                mma_bf16(d, aGl[ks], bFh[ks * 2], bFh[ks * 2 + 1]);
            }
        }

        // ---- PV(tile): O[64q x 16ch] per warp += P . H ----
        {
            uint32_t hb = sb + OFF_H + cur * 33792;
            uint32_t pbase = sb + OFF_P + (tile & 1) * 10240;
            uint32_t bHh[2][4], bHl[2][4];
#pragma unroll
            for (int ks = 0; ks < 2; ks++) {
                uint32_t roff = (uint32_t)(ks * 16 + (sel & 1) * 8 + (l & 7)) * 528 +
                                cb * 2 + (sel >> 1) * 16;
                ldsm4t(bHh[ks], hb + roff);
                ldsm4t(bHl[ks], hb + 16896 + roff);
            }
#pragma unroll
            for (int m2 = 0; m2 < 4; m2++) {
                uint32_t aPh[2][4], aPl[2][4];
#pragma unroll
                for (int ks = 0; ks < 2; ks++) {
                    uint32_t roff = (uint32_t)(m2 * 16 + (sel & 1) * 8 + (l & 7)) * 80 +
                                    ks * 32 + (sel >> 1) * 16;
                    ldsm4(aPh[ks], pbase + roff);
                    ldsm4(aPl[ks], pbase + 5120 + roff);
                }
#pragma unroll
                for (int nt = 0; nt < 2; nt++) {
                    int o2 = nt * 2;
#pragma unroll
                    for (int ks = 0; ks < 2; ks++) {
                        mma_bf16(O[m2][nt], aPh[ks], bHh[ks][o2], bHh[ks][o2 + 1]);
                        mma_bf16(O[m2][nt], aPh[ks], bHl[ks][o2], bHl[ks][o2 + 1]);
                        mma_bf16(O[m2][nt], aPl[ks], bHh[ks][o2], bHh[ks][o2 + 1]);
                    }
                }
            }
        }

        // ---- exp(tile+1) -> P[(tile+1)&1] ----
        if (tile + 1 < 128) {
            float e0 = __expf(d[0]), e1 = __expf(d[1]);
            float e2 = __expf(d[2]), e3 = __expf(d[3]);
            lacc0 += e0 + e1; lacc1 += e2 + e3;
            __nv_bfloat16 h0 = __float2bfloat16(e0), h1 = __float2bfloat16(e1);
            __nv_bfloat16 h2 = __float2bfloat16(e2), h3 = __float2bfloat16(e3);
            uint32_t pb = sb + OFF_P + ((tile + 1) & 1) * 10240;
            STS32(pb + (uint32_t)p_r0 * 80 + p_colb,
                  ((uint32_t)__bfloat16_as_ushort(h1) << 16) | __bfloat16_as_ushort(h0));
            STS32(pb + (uint32_t)(p_r0 + 8) * 80 + p_colb,
                  ((uint32_t)__bfloat16_as_ushort(h3) << 16) | __bfloat16_as_ushort(h2));
            STS32(pb + 5120 + (uint32_t)p_r0 * 80 + p_colb,
                  pkbf(e0 - __bfloat162float(h0), e1 - __bfloat162float(h1)));
            STS32(pb + 5120 + (uint32_t)(p_r0 + 8) * 80 + p_colb,
                  pkbf(e2 - __bfloat162float(h2), e3 - __bfloat162float(h3)));
        }

        int tmp = cur; cur = nxt; nxt = nx2; nx2 = tmp;
    }

    // ---- l reduction: quad shuffle + cross-warp atomic ----
    lacc0 += __shfl_xor_sync(0xffffffffu, lacc0, 1);
    lacc0 += __shfl_xor_sync(0xffffffffu, lacc0, 2);
    lacc1 += __shfl_xor_sync(0xffffffffu, lacc1, 1);
    lacc1 += __shfl_xor_sync(0xffffffffu, lacc1, 2);
    if ((l & 3) == 0) {
        atomicAdd(&lred[mt * 16 + (l >> 2)], lacc0);
        atomicAdd(&lred[mt * 16 + (l >> 2) + 8], lacc1);
    }
    __syncthreads();

    // ---- epilogue: normalize + residual ----
#pragma unroll
    for (int m2 = 0; m2 < 4; m2++) {
        int r0 = m2 * 16 + (l >> 2), r1 = r0 + 8;
        float i0 = 1.0f / lred[r0], i1 = 1.0f / lred[r1];
#pragma unroll
        for (int nt = 0; nt < 2; nt++) {
            int col = cb + nt * 8 + (l & 3) * 2;
            size_t p0 = (qpix + r0) * CC + col;
            size_t p1 = (qpix + r1) * CC + col;
            float2 xv0 = *(const float2*)&x[p0];
            float2 xv1 = *(const float2*)&x[p1];
            float2 ov0, ov1;
            ov0.x = xv0.x + O[m2][nt][0] * i0;
            ov0.y = xv0.y + O[m2][nt][1] * i0;
            ov1.x = xv1.x + O[m2][nt][2] * i1;
            ov1.y = xv1.y + O[m2][nt][3] * i1;
            *(float2*)&out[p0] = ov0;
            *(float2*)&out[p1] = ov1;
        }
    }
}

// =====================================================================
extern "C" void kernel_launch(void* const* d_in, const int* in_sizes, int n_in,
                              void* d_out, int out_size)
{
    const float* x  = (const float*)d_in[0];
    const float* Wf = (const float*)d_in[1];
    const float* bf = (const float*)d_in[2];
    const float* Wg = (const float*)d_in[3];
    const float* bg = (const float*)d_in[4];
    const float* Wh = (const float*)d_in[5];
    const float* bh = (const float*)d_in[6];
    float* out = (float*)d_out;

    cudaFuncSetAttribute(flash3, cudaFuncAttributeMaxDynamicSharedMemorySize, SMEM3);

    proj_kernel<<<BB * NN / 64, 256>>>(x, Wf, bf, Wg, bg, Wh, bh);
    flash3<<<BB * NN / 64, 512, SMEM3>>>(x, out);
}